// round 11
// baseline (speedup 1.0000x reference)
#include <cuda_runtime.h>
#include <cuda_fp16.h>
#include <math.h>

#define BATCH 32
#define CHAN  4
#define Hn    512
#define Wn    512
#define PLANE (Hn * Wn)

// Output layout (flattened tuple, fp32 elements):
#define kMatOff   33554432
#define kInvOff   33554720
#define kGridOff  33555008
#define kIGridOff 50332224

// NHWC fp16x4 packed copy of src: 32*512*512 px * 8B = 64 MB.
__device__ uint2 g_pack[BATCH * PLANE];

// Pack (NCHW fp32 -> NHWC fp16x4, 4 px/thread) + fused matrix build.
__global__ __launch_bounds__(256)
void pack_kernel(const float* __restrict__ src,
                 const float* __restrict__ fc2,
                 float* __restrict__ out) {
    if (blockIdx.x == 0 && threadIdx.x < BATCH) {
        const int b = threadIdx.x;
        const float PI = 3.14159265358979323846f;
        float f0 = fc2[b * 7 + 0];
        float f1 = fc2[b * 7 + 1];
        float f2 = fc2[b * 7 + 2];
        float f3 = fc2[b * 7 + 3];
        float f4 = fc2[b * 7 + 4];
        float f5 = fc2[b * 7 + 5];
        float f6 = fc2[b * 7 + 6];

        float theta = fminf(fmaxf(f0 * 0.3f, -1.0f), 1.0f) * PI;
        float sx    = fminf(fmaxf(f1 * 0.3f + 1.0f, 0.0f), 5.0f);
        float sy    = fminf(fmaxf(f2 * 0.3f + 1.0f, 0.0f), 5.0f);
        float tx    = f3 * 0.3f;
        float ty    = f4 * 0.3f;
        float shxy  = fminf(fmaxf(f5 * 0.3f, -1.0f), 1.0f) * PI;
        float shyx  = fminf(fmaxf(f6 * 0.3f, -1.0f), 1.0f) * PI;

        float c = cosf(theta);
        float s = sinf(theta);

        float m00 = sx * c + shxy * sy * s;
        float m01 = -sx * s + shxy * sy * c;
        float m10 = shyx * sx * c + sy * s;
        float m11 = -shyx * sx * s + sy * c;

        float det  = m00 * m11 - m01 * m10;
        float rdet = 1.0f / det;
        float i00 =  m11 * rdet;
        float i01 = -m01 * rdet;
        float i10 = -m10 * rdet;
        float i11 =  m00 * rdet;
        float i02 = (m01 * ty - m11 * tx) * rdet;
        float i12 = (m10 * tx - m00 * ty) * rdet;

        float* M = out + kMatOff + b * 9;
        M[0] = m00; M[1] = m01; M[2] = tx;
        M[3] = m10; M[4] = m11; M[5] = ty;
        M[6] = 0.0f; M[7] = 0.0f; M[8] = 1.0f;

        float* I = out + kInvOff + b * 9;
        I[0] = i00; I[1] = i01; I[2] = i02;
        I[3] = i10; I[4] = i11; I[5] = i12;
        I[6] = 0.0f; I[7] = 0.0f; I[8] = 1.0f;
    }

    int t = blockIdx.x * 256 + threadIdx.x;
    int idx4 = t * 4;
    int b    = idx4 >> 18;
    int rem  = idx4 & (PLANE - 1);

    const float* base = src + b * CHAN * PLANE + rem;
    float4 v0 = __ldcs(reinterpret_cast<const float4*>(base));
    float4 v1 = __ldcs(reinterpret_cast<const float4*>(base + PLANE));
    float4 v2 = __ldcs(reinterpret_cast<const float4*>(base + 2 * PLANE));
    float4 v3 = __ldcs(reinterpret_cast<const float4*>(base + 3 * PLANE));

    uint2 p[4];
    {
        __half2 a, bb;
        a = __floats2half2_rn(v0.x, v1.x); bb = __floats2half2_rn(v2.x, v3.x);
        p[0].x = *reinterpret_cast<unsigned*>(&a); p[0].y = *reinterpret_cast<unsigned*>(&bb);
        a = __floats2half2_rn(v0.y, v1.y); bb = __floats2half2_rn(v2.y, v3.y);
        p[1].x = *reinterpret_cast<unsigned*>(&a); p[1].y = *reinterpret_cast<unsigned*>(&bb);
        a = __floats2half2_rn(v0.z, v1.z); bb = __floats2half2_rn(v2.z, v3.z);
        p[2].x = *reinterpret_cast<unsigned*>(&a); p[2].y = *reinterpret_cast<unsigned*>(&bb);
        a = __floats2half2_rn(v0.w, v1.w); bb = __floats2half2_rn(v2.w, v3.w);
        p[3].x = *reinterpret_cast<unsigned*>(&a); p[3].y = *reinterpret_cast<unsigned*>(&bb);
    }
    uint4* dst = reinterpret_cast<uint4*>(g_pack + idx4);
    dst[0] = make_uint4(p[0].x, p[0].y, p[1].x, p[1].y);
    dst[1] = make_uint4(p[2].x, p[2].y, p[3].x, p[3].y);
}

static __device__ __forceinline__ __half2 h2(unsigned u) {
    return *reinterpret_cast<__half2*>(&u);
}

// Fast-path sample: interior guaranteed, half2 blend (channels packed 2+2).
static __device__ __forceinline__ void sample_fast(
    const uint2* __restrict__ pk, float ix, float iy, float* r)
{
    const float x0f = floorf(ix), y0f = floorf(iy);
    const float wx = ix - x0f, wy = iy - y0f;
    const int xi0 = (int)x0f, yi0 = (int)y0f;

    const uint2* p = pk + yi0 * Wn + xi0;
    uint2 a = __ldg(p);
    uint2 bq = __ldg(p + 1);
    uint2 cq = __ldg(p + Wn);
    uint2 dq = __ldg(p + Wn + 1);

    const float u0 = 1.0f - wx, t0 = 1.0f - wy;
    __half2 w00h = __float2half2_rn(u0 * t0);
    __half2 w01h = __float2half2_rn(wx * t0);
    __half2 w10h = __float2half2_rn(u0 * wy);
    __half2 w11h = __float2half2_rn(wx * wy);

    __half2 accl = __hmul2(h2(a.x), w00h);
    accl = __hfma2(h2(bq.x), w01h, accl);
    accl = __hfma2(h2(cq.x), w10h, accl);
    accl = __hfma2(h2(dq.x), w11h, accl);
    __half2 acch = __hmul2(h2(a.y), w00h);
    acch = __hfma2(h2(bq.y), w01h, acch);
    acch = __hfma2(h2(cq.y), w10h, acch);
    acch = __hfma2(h2(dq.y), w11h, acch);

    float2 r01 = __half22float2(accl);
    float2 r23 = __half22float2(acch);
    r[0] = r01.x; r[1] = r01.y; r[2] = r23.x; r[3] = r23.y;
}

static __device__ __forceinline__ float4 unpack_h4(uint2 u) {
    float2 a = __half22float2(h2(u.x));
    float2 c = __half22float2(h2(u.y));
    return make_float4(a.x, a.y, c.x, c.y);
}

// Slow-path sample: masked/clamped, fp32 blend.
static __device__ __forceinline__ void sample_slow(
    const uint2* __restrict__ pk, float ix, float iy, float* r)
{
    const float x0f = floorf(ix), y0f = floorf(iy);
    const float wx = ix - x0f, wy = iy - y0f;
    const int xi0 = (int)x0f, yi0 = (int)y0f;
    const int xi1 = xi0 + 1,  yi1 = yi0 + 1;

    const float vx0 = (xi0 >= 0 && xi0 < Wn) ? 1.0f : 0.0f;
    const float vx1 = (xi1 >= 0 && xi1 < Wn) ? 1.0f : 0.0f;
    const float vy0 = (yi0 >= 0 && yi0 < Hn) ? 1.0f : 0.0f;
    const float vy1 = (yi1 >= 0 && yi1 < Hn) ? 1.0f : 0.0f;

    const int cx0 = min(max(xi0, 0), Wn - 1);
    const int cx1 = min(max(xi1, 0), Wn - 1);
    const int cy0 = min(max(yi0, 0), Hn - 1);
    const int cy1 = min(max(yi1, 0), Hn - 1);

    const float w00 = (1.0f - wx) * (1.0f - wy) * vx0 * vy0;
    const float w01 = wx * (1.0f - wy) * vx1 * vy0;
    const float w10 = (1.0f - wx) * wy * vx0 * vy1;
    const float w11 = wx * wy * vx1 * vy1;

    float4 v00 = unpack_h4(__ldg(pk + cy0 * Wn + cx0));
    float4 v01 = unpack_h4(__ldg(pk + cy0 * Wn + cx1));
    float4 v10 = unpack_h4(__ldg(pk + cy1 * Wn + cx0));
    float4 v11 = unpack_h4(__ldg(pk + cy1 * Wn + cx1));

    r[0] = fmaf(v00.x, w00, fmaf(v01.x, w01, fmaf(v10.x, w10, v11.x * w11)));
    r[1] = fmaf(v00.y, w00, fmaf(v01.y, w01, fmaf(v10.y, w10, v11.y * w11)));
    r[2] = fmaf(v00.z, w00, fmaf(v01.z, w01, fmaf(v10.z, w10, v11.z * w11)));
    r[3] = fmaf(v00.w, w00, fmaf(v01.w, w01, fmaf(v10.w, w10, v11.w * w11)));
}

// Block tile: 64(x) x 16(y), 256 threads, 4 x-adjacent px/thread.
// Warp footprint: 32x4 px. Transformed: STG.128 with full 128B row segments.
// All output stores streaming (__stcs) to keep the pack buffer L2-resident.
__global__ __launch_bounds__(256)
void affine_main_kernel(float* __restrict__ out) {
    const int b  = blockIdx.z;
    const int bx = blockIdx.x * 64;
    const int by = blockIdx.y * 16;
    const int tid  = threadIdx.x;
    const int warp = tid >> 5;
    const int lane = tid & 31;

    __shared__ float sm[12];
    if (tid < 6) {
        sm[tid]     = out[kMatOff + b * 9 + tid];
        sm[tid + 6] = out[kInvOff + b * 9 + tid];
    }
    __syncthreads();

    const float m00 = sm[0], m01 = sm[1], m02 = sm[2];
    const float m10 = sm[3], m11 = sm[4], m12 = sm[5];

    // Pixel-space coefficients: ix = m00*x + m01*y + Cx
    const float Cx = fmaf(-255.5f, m00 + m01, fmaf(256.0f, m02, 255.5f));
    const float Cy = fmaf(-255.5f, m10 + m11, fmaf(256.0f, m12, 255.5f));

    // warp footprint 32x4: lane&7 -> x-group (4 px), lane>>3 -> row
    const int cx = bx + ((warp & 1) << 5) + ((lane & 7) << 2);
    const int cy = by + ((warp >> 1) << 2) + (lane >> 3);
    const float fx0 = (float)cx;
    const float fy  = (float)cy;

    float ix[4], iy[4];
    ix[0] = fmaf(m00, fx0, fmaf(m01, fy, Cx));
    iy[0] = fmaf(m10, fx0, fmaf(m11, fy, Cy));
    #pragma unroll
    for (int k = 1; k < 4; k++) { ix[k] = ix[k-1] + m00; iy[k] = iy[k-1] + m10; }

    // Block-uniform interior test: center +- radius (linear map => exact).
    const float cxm = (float)bx + 31.5f, cym = (float)by + 7.5f;
    const float ecx = fmaf(m00, cxm, fmaf(m01, cym, Cx));
    const float ecy = fmaf(m10, cxm, fmaf(m11, cym, Cy));
    const float rx = fabsf(m00) * 31.5f + fabsf(m01) * 7.5f;
    const float ry = fabsf(m10) * 31.5f + fabsf(m11) * 7.5f;
    const bool interior = (ecx - rx >= 0.01f) & (ecx + rx <= 509.99f) &
                          (ecy - ry >= 0.01f) & (ecy + ry <= 509.99f);

    const uint2* pk = g_pack + b * PLANE;
    float r[4][4];
    if (interior) {
        #pragma unroll
        for (int k = 0; k < 4; k++) sample_fast(pk, ix[k], iy[k], r[k]);
    } else {
        #pragma unroll
        for (int k = 0; k < 4; k++) sample_slow(pk, ix[k], iy[k], r[k]);
    }

    // transformed: 4 x STG.128 (one per channel plane), streaming.
    {
        int base0 = (b * CHAN * Hn + cy) * Wn + cx;
        #pragma unroll
        for (int ch = 0; ch < CHAN; ch++) {
            float4 v = make_float4(r[0][ch], r[1][ch], r[2][ch], r[3][ch]);
            __stcs(reinterpret_cast<float4*>(out + base0 + ch * PLANE), v);
        }
    }

    const int pix = (b * Hn + cy) * Wn + cx;
    const float kk = 0.00390625f;        // 1/256
    const float c0 = -0.998046875f;      // -255.5/256

    // grid: normalize pixel-space coords (2 x STG.128, streaming).
    {
        float4 g0 = make_float4(fmaf(ix[0], kk, c0), fmaf(iy[0], kk, c0),
                                fmaf(ix[1], kk, c0), fmaf(iy[1], kk, c0));
        float4 g1 = make_float4(fmaf(ix[2], kk, c0), fmaf(iy[2], kk, c0),
                                fmaf(ix[3], kk, c0), fmaf(iy[3], kk, c0));
        __stcs(reinterpret_cast<float4*>(out + kGridOff + pix * 2), g0);
        __stcs(reinterpret_cast<float4*>(out + kGridOff + pix * 2 + 4), g1);
    }

    // inv_grid: normalized affine with inverse matrix (2 x STG.128, streaming).
    {
        const float i00 = sm[6], i01 = sm[7], i02 = sm[8];
        const float i10 = sm[9], i11 = sm[10], i12 = sm[11];
        const float ypn = fmaf(fy, kk, c0);
        float xpn[4];
        xpn[0] = fmaf(fx0, kk, c0);
        #pragma unroll
        for (int k = 1; k < 4; k++) xpn[k] = xpn[k-1] + kk;

        float4 g0 = make_float4(fmaf(i00, xpn[0], fmaf(i01, ypn, i02)),
                                fmaf(i10, xpn[0], fmaf(i11, ypn, i12)),
                                fmaf(i00, xpn[1], fmaf(i01, ypn, i02)),
                                fmaf(i10, xpn[1], fmaf(i11, ypn, i12)));
        float4 g1 = make_float4(fmaf(i00, xpn[2], fmaf(i01, ypn, i02)),
                                fmaf(i10, xpn[2], fmaf(i11, ypn, i12)),
                                fmaf(i00, xpn[3], fmaf(i01, ypn, i02)),
                                fmaf(i10, xpn[3], fmaf(i11, ypn, i12)));
        __stcs(reinterpret_cast<float4*>(out + kIGridOff + pix * 2), g0);
        __stcs(reinterpret_cast<float4*>(out + kIGridOff + pix * 2 + 4), g1);
    }
}

extern "C" void kernel_launch(void* const* d_in, const int* in_sizes, int n_in,
                              void* d_out, int out_size) {
    const float* src = (const float*)d_in[0];
    const float* fc2 = (const float*)d_in[1];
    float* out = (float*)d_out;

    // Exactly 2 launches per call so ncu's capture (launch #4) = affine_main.
    pack_kernel<<<(BATCH * PLANE) / (256 * 4), 256>>>(src, fc2, out);

    dim3 grid(Wn / 64, Hn / 16, BATCH);
    affine_main_kernel<<<grid, 256>>>(out);
}

// round 12
// speedup vs baseline: 1.0274x; 1.0274x over previous
#include <cuda_runtime.h>
#include <cuda_fp16.h>
#include <math.h>

#define BATCH 32
#define CHAN  4
#define Hn    512
#define Wn    512
#define PLANE (Hn * Wn)

// Output layout (flattened tuple, fp32 elements):
#define kMatOff   33554432
#define kInvOff   33554720
#define kGridOff  33555008
#define kIGridOff 50332224

// NHWC fp16x4 packed copy of src: 32*512*512 px * 8B = 64 MB.
__device__ uint2 g_pack[BATCH * PLANE];

// Pack (NCHW fp32 -> NHWC fp16x4, 4 px/thread) + fused matrix build.
__global__ __launch_bounds__(256)
void pack_kernel(const float* __restrict__ src,
                 const float* __restrict__ fc2,
                 float* __restrict__ out) {
    if (blockIdx.x == 0 && threadIdx.x < BATCH) {
        const int b = threadIdx.x;
        const float PI = 3.14159265358979323846f;
        float f0 = fc2[b * 7 + 0];
        float f1 = fc2[b * 7 + 1];
        float f2 = fc2[b * 7 + 2];
        float f3 = fc2[b * 7 + 3];
        float f4 = fc2[b * 7 + 4];
        float f5 = fc2[b * 7 + 5];
        float f6 = fc2[b * 7 + 6];

        float theta = fminf(fmaxf(f0 * 0.3f, -1.0f), 1.0f) * PI;
        float sx    = fminf(fmaxf(f1 * 0.3f + 1.0f, 0.0f), 5.0f);
        float sy    = fminf(fmaxf(f2 * 0.3f + 1.0f, 0.0f), 5.0f);
        float tx    = f3 * 0.3f;
        float ty    = f4 * 0.3f;
        float shxy  = fminf(fmaxf(f5 * 0.3f, -1.0f), 1.0f) * PI;
        float shyx  = fminf(fmaxf(f6 * 0.3f, -1.0f), 1.0f) * PI;

        float c = cosf(theta);
        float s = sinf(theta);

        float m00 = sx * c + shxy * sy * s;
        float m01 = -sx * s + shxy * sy * c;
        float m10 = shyx * sx * c + sy * s;
        float m11 = -shyx * sx * s + sy * c;

        float det  = m00 * m11 - m01 * m10;
        float rdet = 1.0f / det;
        float i00 =  m11 * rdet;
        float i01 = -m01 * rdet;
        float i10 = -m10 * rdet;
        float i11 =  m00 * rdet;
        float i02 = (m01 * ty - m11 * tx) * rdet;
        float i12 = (m10 * tx - m00 * ty) * rdet;

        float* M = out + kMatOff + b * 9;
        M[0] = m00; M[1] = m01; M[2] = tx;
        M[3] = m10; M[4] = m11; M[5] = ty;
        M[6] = 0.0f; M[7] = 0.0f; M[8] = 1.0f;

        float* I = out + kInvOff + b * 9;
        I[0] = i00; I[1] = i01; I[2] = i02;
        I[3] = i10; I[4] = i11; I[5] = i12;
        I[6] = 0.0f; I[7] = 0.0f; I[8] = 1.0f;
    }

    int t = blockIdx.x * 256 + threadIdx.x;
    int idx4 = t * 4;
    int b    = idx4 >> 18;
    int rem  = idx4 & (PLANE - 1);

    const float* base = src + b * CHAN * PLANE + rem;
    float4 v0 = __ldcs(reinterpret_cast<const float4*>(base));
    float4 v1 = __ldcs(reinterpret_cast<const float4*>(base + PLANE));
    float4 v2 = __ldcs(reinterpret_cast<const float4*>(base + 2 * PLANE));
    float4 v3 = __ldcs(reinterpret_cast<const float4*>(base + 3 * PLANE));

    uint2 p[4];
    {
        __half2 a, bb;
        a = __floats2half2_rn(v0.x, v1.x); bb = __floats2half2_rn(v2.x, v3.x);
        p[0].x = *reinterpret_cast<unsigned*>(&a); p[0].y = *reinterpret_cast<unsigned*>(&bb);
        a = __floats2half2_rn(v0.y, v1.y); bb = __floats2half2_rn(v2.y, v3.y);
        p[1].x = *reinterpret_cast<unsigned*>(&a); p[1].y = *reinterpret_cast<unsigned*>(&bb);
        a = __floats2half2_rn(v0.z, v1.z); bb = __floats2half2_rn(v2.z, v3.z);
        p[2].x = *reinterpret_cast<unsigned*>(&a); p[2].y = *reinterpret_cast<unsigned*>(&bb);
        a = __floats2half2_rn(v0.w, v1.w); bb = __floats2half2_rn(v2.w, v3.w);
        p[3].x = *reinterpret_cast<unsigned*>(&a); p[3].y = *reinterpret_cast<unsigned*>(&bb);
    }
    uint4* dst = reinterpret_cast<uint4*>(g_pack + idx4);
    dst[0] = make_uint4(p[0].x, p[0].y, p[1].x, p[1].y);
    dst[1] = make_uint4(p[2].x, p[2].y, p[3].x, p[3].y);
}

static __device__ __forceinline__ __half2 h2(unsigned u) {
    return *reinterpret_cast<__half2*>(&u);
}

// Fast-path sample: interior guaranteed, half2 blend (channels packed 2+2).
static __device__ __forceinline__ void sample_fast(
    const uint2* __restrict__ pk, float ix, float iy, float* r)
{
    const float x0f = floorf(ix), y0f = floorf(iy);
    const float wx = ix - x0f, wy = iy - y0f;
    const int xi0 = (int)x0f, yi0 = (int)y0f;

    const uint2* p = pk + yi0 * Wn + xi0;
    uint2 a = __ldg(p);
    uint2 bq = __ldg(p + 1);
    uint2 cq = __ldg(p + Wn);
    uint2 dq = __ldg(p + Wn + 1);

    const float u0 = 1.0f - wx, t0 = 1.0f - wy;
    __half2 w00h = __float2half2_rn(u0 * t0);
    __half2 w01h = __float2half2_rn(wx * t0);
    __half2 w10h = __float2half2_rn(u0 * wy);
    __half2 w11h = __float2half2_rn(wx * wy);

    __half2 accl = __hmul2(h2(a.x), w00h);
    accl = __hfma2(h2(bq.x), w01h, accl);
    accl = __hfma2(h2(cq.x), w10h, accl);
    accl = __hfma2(h2(dq.x), w11h, accl);
    __half2 acch = __hmul2(h2(a.y), w00h);
    acch = __hfma2(h2(bq.y), w01h, acch);
    acch = __hfma2(h2(cq.y), w10h, acch);
    acch = __hfma2(h2(dq.y), w11h, acch);

    float2 r01 = __half22float2(accl);
    float2 r23 = __half22float2(acch);
    r[0] = r01.x; r[1] = r01.y; r[2] = r23.x; r[3] = r23.y;
}

static __device__ __forceinline__ float4 unpack_h4(uint2 u) {
    float2 a = __half22float2(h2(u.x));
    float2 c = __half22float2(h2(u.y));
    return make_float4(a.x, a.y, c.x, c.y);
}

// Slow-path sample: masked/clamped, fp32 blend.
static __device__ __forceinline__ void sample_slow(
    const uint2* __restrict__ pk, float ix, float iy, float* r)
{
    const float x0f = floorf(ix), y0f = floorf(iy);
    const float wx = ix - x0f, wy = iy - y0f;
    const int xi0 = (int)x0f, yi0 = (int)y0f;
    const int xi1 = xi0 + 1,  yi1 = yi0 + 1;

    const float vx0 = (xi0 >= 0 && xi0 < Wn) ? 1.0f : 0.0f;
    const float vx1 = (xi1 >= 0 && xi1 < Wn) ? 1.0f : 0.0f;
    const float vy0 = (yi0 >= 0 && yi0 < Hn) ? 1.0f : 0.0f;
    const float vy1 = (yi1 >= 0 && yi1 < Hn) ? 1.0f : 0.0f;

    const int cx0 = min(max(xi0, 0), Wn - 1);
    const int cx1 = min(max(xi1, 0), Wn - 1);
    const int cy0 = min(max(yi0, 0), Hn - 1);
    const int cy1 = min(max(yi1, 0), Hn - 1);

    const float w00 = (1.0f - wx) * (1.0f - wy) * vx0 * vy0;
    const float w01 = wx * (1.0f - wy) * vx1 * vy0;
    const float w10 = (1.0f - wx) * wy * vx0 * vy1;
    const float w11 = wx * wy * vx1 * vy1;

    float4 v00 = unpack_h4(__ldg(pk + cy0 * Wn + cx0));
    float4 v01 = unpack_h4(__ldg(pk + cy0 * Wn + cx1));
    float4 v10 = unpack_h4(__ldg(pk + cy1 * Wn + cx0));
    float4 v11 = unpack_h4(__ldg(pk + cy1 * Wn + cx1));

    r[0] = fmaf(v00.x, w00, fmaf(v01.x, w01, fmaf(v10.x, w10, v11.x * w11)));
    r[1] = fmaf(v00.y, w00, fmaf(v01.y, w01, fmaf(v10.y, w10, v11.y * w11)));
    r[2] = fmaf(v00.z, w00, fmaf(v01.z, w01, fmaf(v10.z, w10, v11.z * w11)));
    r[3] = fmaf(v00.w, w00, fmaf(v01.w, w01, fmaf(v10.w, w10, v11.w * w11)));
}

// Block tile: 64(x) x 8(y), 256 threads, 2 x-adjacent px/thread.
// Warp footprint: 16x4 px. Direct vectorized stores, streaming (__stcs).
// min-blocks 6 guard keeps regs <= 40 so occupancy stays high.
__global__ __launch_bounds__(256, 6)
void affine_main_kernel(float* __restrict__ out) {
    const int b  = blockIdx.z;
    const int bx = blockIdx.x * 64;
    const int by = blockIdx.y * 8;
    const int tid  = threadIdx.x;
    const int warp = tid >> 5;
    const int lane = tid & 31;

    __shared__ float sm[12];
    if (tid < 6) {
        sm[tid]     = out[kMatOff + b * 9 + tid];
        sm[tid + 6] = out[kInvOff + b * 9 + tid];
    }
    __syncthreads();

    const float m00 = sm[0], m01 = sm[1], m02 = sm[2];
    const float m10 = sm[3], m11 = sm[4], m12 = sm[5];

    // Pixel-space coefficients: ix = m00*x + m01*y + Cx
    const float Cx = fmaf(-255.5f, m00 + m01, fmaf(256.0f, m02, 255.5f));
    const float Cy = fmaf(-255.5f, m10 + m11, fmaf(256.0f, m12, 255.5f));

    const int cx = bx + ((warp & 3) << 4) + ((lane & 7) << 1);  // even
    const int cy = by + ((warp >> 2) << 2) + (lane >> 3);
    const float fx0 = (float)cx;
    const float fy  = (float)cy;

    const float ix0 = fmaf(m00, fx0, fmaf(m01, fy, Cx));
    const float iy0 = fmaf(m10, fx0, fmaf(m11, fy, Cy));
    const float ix1 = ix0 + m00;
    const float iy1 = iy0 + m10;

    // Block-uniform interior test: center +- radius (linear map => exact).
    const float cxm = (float)bx + 31.5f, cym = (float)by + 3.5f;
    const float ecx = fmaf(m00, cxm, fmaf(m01, cym, Cx));
    const float ecy = fmaf(m10, cxm, fmaf(m11, cym, Cy));
    const float rx = fabsf(m00) * 31.5f + fabsf(m01) * 3.5f;
    const float ry = fabsf(m10) * 31.5f + fabsf(m11) * 3.5f;
    const bool interior = (ecx - rx >= 0.01f) & (ecx + rx <= 509.99f) &
                          (ecy - ry >= 0.01f) & (ecy + ry <= 509.99f);

    const uint2* pk = g_pack + b * PLANE;
    float r0[4], r1[4];
    if (interior) {
        sample_fast(pk, ix0, iy0, r0);
        sample_fast(pk, ix1, iy1, r1);
    } else {
        sample_slow(pk, ix0, iy0, r0);
        sample_slow(pk, ix1, iy1, r1);
    }

    // transformed: 4 x STG.64 (channel planes), streaming.
    {
        int base0 = (b * CHAN * Hn + cy) * Wn + cx;
        __stcs(reinterpret_cast<float2*>(out + base0),             make_float2(r0[0], r1[0]));
        __stcs(reinterpret_cast<float2*>(out + base0 + PLANE),     make_float2(r0[1], r1[1]));
        __stcs(reinterpret_cast<float2*>(out + base0 + 2 * PLANE), make_float2(r0[2], r1[2]));
        __stcs(reinterpret_cast<float2*>(out + base0 + 3 * PLANE), make_float2(r0[3], r1[3]));
    }

    const int pix = (b * Hn + cy) * Wn + cx;
    const float kk = 0.00390625f;        // 1/256
    const float c0 = -0.998046875f;      // -255.5/256

    // grid: normalize pixel-space coords (STG.128, streaming).
    {
        float4 g = make_float4(fmaf(ix0, kk, c0), fmaf(iy0, kk, c0),
                               fmaf(ix1, kk, c0), fmaf(iy1, kk, c0));
        __stcs(reinterpret_cast<float4*>(out + kGridOff + pix * 2), g);
    }

    // inv_grid: normalized affine with inverse matrix (STG.128, streaming).
    {
        const float i00 = sm[6], i01 = sm[7], i02 = sm[8];
        const float i10 = sm[9], i11 = sm[10], i12 = sm[11];
        const float xpn0 = fmaf(fx0, kk, c0);
        const float xpn1 = xpn0 + kk;
        const float ypn  = fmaf(fy, kk, c0);
        float4 g;
        g.x = fmaf(i00, xpn0, fmaf(i01, ypn, i02));
        g.y = fmaf(i10, xpn0, fmaf(i11, ypn, i12));
        g.z = fmaf(i00, xpn1, fmaf(i01, ypn, i02));
        g.w = fmaf(i10, xpn1, fmaf(i11, ypn, i12));
        __stcs(reinterpret_cast<float4*>(out + kIGridOff + pix * 2), g);
    }
}

extern "C" void kernel_launch(void* const* d_in, const int* in_sizes, int n_in,
                              void* d_out, int out_size) {
    const float* src = (const float*)d_in[0];
    const float* fc2 = (const float*)d_in[1];
    float* out = (float*)d_out;

    // Exactly 2 launches per call so ncu's capture (launch #4) = affine_main.
    pack_kernel<<<(BATCH * PLANE) / (256 * 4), 256>>>(src, fc2, out);

    dim3 grid(Wn / 64, Hn / 8, BATCH);
    affine_main_kernel<<<grid, 256>>>(out);
}